// round 14
// baseline (speedup 1.0000x reference)
#include <cuda_runtime.h>
#include <cstdint>

// Problem constants (shapes fixed by the dataset)
#define NMAX 50000
#define EMAX 1000000
#define DIN 64
#define H1 64
#define H2 64
#define RNUM 8
#define BNUM 30
#define SCAN_B 256

// ---------------- device scratch (static: no allocs allowed) ----------------
__device__ float4 g_xr[(size_t)NMAX * 512 / 4];    // [N, R*H1] = [N,512]  ~102MB
__device__ float4 g_agg1[(size_t)NMAX * 64 / 4];   // RGCN aggregation
__device__ float4 g_agg2[(size_t)NMAX * 64 / 4];   // GraphConv aggregation
__device__ float4 g_hs[(size_t)NMAX * 64 / 4];     // h * rsqrt(deg_out)
__device__ int    g_deg_out[NMAX];
__device__ int    g_deg_in[NMAX];
__device__ float  g_wrelT[64 * 512];               // [k][r*64+o]
__device__ int    g_src[EMAX];
__device__ int    g_dst[EMAX];
__device__ int    g_et [EMAX];
__device__ int    g_rowstart[NMAX + 1];            // CSR by dst
__device__ int    g_blocksum[1024];
__device__ int    g_fill[NMAX];
__device__ int2   g_edge[EMAX];                    // (src, etype) CSR payload
__device__ int    g_ei_is64;
__device__ int    g_et_sel;
__device__ int    g_et_is64;

// ---------------- dtype + identity detection (1 thread, byte-safe) ----------------
__device__ int valid64_probe(const void* p, int cnt, long long hi) {
    const long long* a = (const long long*)p;
    int stride = cnt > 64 ? cnt / 64 : 1;
    for (int i = 0; i < 64; i++) {
        int idx = i * stride;
        if (idx >= cnt) break;
        long long v = a[idx];
        if (v < 0 || v >= hi) return 0;
    }
    return 1;
}
__device__ int valid32_probe(const void* p, int cnt, int hi) {
    const int* a = (const int*)p;
    int stride = cnt > 64 ? cnt / 64 : 1;
    for (int i = 0; i < 64; i++) {
        int idx = i * stride;
        if (idx >= cnt) break;
        int v = a[idx];
        if (v < 0 || v >= hi) return 0;
    }
    return 1;
}
__global__ void detect_kernel(const void* ei, const void* etA, const void* etB,
                              int E, int N) {
    g_ei_is64 = valid64_probe(ei, E, N);
    int A32 = valid32_probe(etA, E, 64);
    int A64 = valid64_probe(etA, E / 2, 64);
    int B32 = valid32_probe(etB, E, 64);
    int B64 = valid64_probe(etB, E / 2, 64);
    int selA = (A32 || A64);
    int selB = (B32 || B64);
    if (selA && !selB)      { g_et_sel = 0; g_et_is64 = A64; }
    else if (selB && !selA) { g_et_sel = 1; g_et_is64 = B64; }
    else                    { g_et_sel = 1; g_et_is64 = B64; }
}

// ---------------- zero counters ----------------
__global__ void zero_kernel(int n) {
    int i = blockIdx.x * blockDim.x + threadIdx.x;
    if (i < n) { g_deg_out[i] = 0; g_deg_in[i] = 0; g_fill[i] = 0; }
}

// ---------------- convert indices + degree counts (clamped: no traps) ----------------
__global__ void convert_kernel(const void* ei, const void* etA, const void* etB,
                               int E, int N) {
    int e = blockIdx.x * blockDim.x + threadIdx.x;
    if (e >= E) return;
    const void* et = g_et_sel ? etB : etA;
    long long s, d, r;
    if (g_ei_is64) {
        s = ((const long long*)ei)[e];
        d = ((const long long*)ei)[E + e];
    } else {
        s = ((const int*)ei)[e];
        d = ((const int*)ei)[E + e];
    }
    if (g_et_is64) r = ((const long long*)et)[e];
    else           r = ((const int*)et)[e];
    int si = (int)s, di = (int)d, ri = (int)r;
    if (si < 0) si = 0; if (si >= N) si = N - 1;
    if (di < 0) di = 0; if (di >= N) di = N - 1;
    ri &= 7;
    g_src[e] = si; g_dst[e] = di; g_et[e] = ri;
    atomicAdd(&g_deg_out[si], 1);
    atomicAdd(&g_deg_in[di], 1);
}

// ---------------- exclusive scan of deg_in -> rowstart (3 kernels) ----------------
__global__ void scanA_kernel(int n) {
    __shared__ int sh[SCAN_B];
    int i = blockIdx.x * SCAN_B + threadIdx.x;
    int v = (i < n) ? g_deg_in[i] : 0;
    sh[threadIdx.x] = v;
    __syncthreads();
#pragma unroll
    for (int off = 1; off < SCAN_B; off <<= 1) {
        int t = (threadIdx.x >= off) ? sh[threadIdx.x - off] : 0;
        __syncthreads();
        sh[threadIdx.x] += t;
        __syncthreads();
    }
    if (i < n) g_rowstart[i] = sh[threadIdx.x] - v;       // exclusive
    if (threadIdx.x == SCAN_B - 1) g_blocksum[blockIdx.x] = sh[threadIdx.x];
}
__global__ void scanB_kernel(int nb) {   // nb <= 1024, one block of 1024
    __shared__ int sh[1024];
    int v = (threadIdx.x < nb) ? g_blocksum[threadIdx.x] : 0;
    sh[threadIdx.x] = v;
    __syncthreads();
#pragma unroll
    for (int off = 1; off < 1024; off <<= 1) {
        int t = (threadIdx.x >= off) ? sh[threadIdx.x - off] : 0;
        __syncthreads();
        sh[threadIdx.x] += t;
        __syncthreads();
    }
    if (threadIdx.x < nb) g_blocksum[threadIdx.x] = sh[threadIdx.x] - v;  // exclusive
}
__global__ void scanC_kernel(int n, int E) {
    int i = blockIdx.x * SCAN_B + threadIdx.x;
    if (i < n) g_rowstart[i] += g_blocksum[blockIdx.x];
    if (i == 0) g_rowstart[n] = E;
}

// ---------------- CSR fill: slot per edge under its dst row ----------------
__global__ void fill_kernel(int E) {
    int e = blockIdx.x * blockDim.x + threadIdx.x;
    if (e >= E) return;
    int d = g_dst[e];
    int slot = g_rowstart[d] + atomicAdd(&g_fill[d], 1);
    g_edge[slot] = make_int2(g_src[e], g_et[e]);
}

// ---------------- Wrel^T, stored [k][r*64+o] ----------------
__global__ void wrel_kernel(const float* __restrict__ comp,
                            const float* __restrict__ basis) {
    int idx = blockIdx.x * blockDim.x + threadIdx.x;
    if (idx >= 64 * 512) return;
    int k = idx >> 9;
    int rem = idx & 511;
    int r = rem >> 6;
    int o = rem & 63;
    float s = 0.f;
#pragma unroll
    for (int b = 0; b < BNUM; b++)
        s = fmaf(comp[r * BNUM + b], basis[b * (DIN * H1) + k * H1 + o], s);
    g_wrelT[idx] = s;
}

// ---------------- big GEMM (xr): C[M,512] = A[M,64] @ B[64,512] ----------------
// Tile 128x128, 256 threads, 8x8 microtile, K slabs of 32.
__global__ __launch_bounds__(256) void gemm_xr(
    const float* __restrict__ A, const float* __restrict__ B,
    float* __restrict__ C, int M)
{
    __shared__ float As[32][132];
    __shared__ float Bs[32][128];

    const int tid = threadIdx.x;
    const int row0 = blockIdx.y * 128;
    const int col0 = blockIdx.x * 128;

    float acc[8][8];
#pragma unroll
    for (int r = 0; r < 8; r++)
#pragma unroll
        for (int c = 0; c < 8; c++) acc[r][c] = 0.f;

    const int tm = tid >> 4;
    const int tn = tid & 15;

    for (int ks = 0; ks < 64; ks += 32) {
#pragma unroll
        for (int i = 0; i < 4; i++) {
            int j = tid + i * 256;
            int r = j >> 3;
            int c4 = j & 7;
            int row = row0 + r;
            float4 v = make_float4(0.f, 0.f, 0.f, 0.f);
            if (row < M)
                v = *(const float4*)(A + (size_t)row * 64 + ks + c4 * 4);
            As[c4 * 4 + 0][r] = v.x;
            As[c4 * 4 + 1][r] = v.y;
            As[c4 * 4 + 2][r] = v.z;
            As[c4 * 4 + 3][r] = v.w;
        }
#pragma unroll
        for (int i = 0; i < 4; i++) {
            int j = tid + i * 256;
            int r = j >> 5;
            int c4 = j & 31;
            *(float4*)&Bs[r][c4 * 4] =
                *(const float4*)(B + (size_t)(ks + r) * 512 + col0 + c4 * 4);
        }
        __syncthreads();

#pragma unroll
        for (int k = 0; k < 32; k++) {
            float a[8], b[8];
            *(float4*)&a[0] = *(const float4*)&As[k][tm * 8];
            *(float4*)&a[4] = *(const float4*)&As[k][tm * 8 + 4];
            *(float4*)&b[0] = *(const float4*)&Bs[k][tn * 8];
            *(float4*)&b[4] = *(const float4*)&Bs[k][tn * 8 + 4];
#pragma unroll
            for (int r = 0; r < 8; r++)
#pragma unroll
                for (int c = 0; c < 8; c++)
                    acc[r][c] = fmaf(a[r], b[c], acc[r][c]);
        }
        __syncthreads();
    }

#pragma unroll
    for (int r = 0; r < 8; r++) {
        int row = row0 + tm * 8 + r;
        if (row >= M) break;
        float* crow = C + (size_t)row * 512 + col0 + tn * 8;
        *(float4*)(crow)     = *(float4*)&acc[r][0];
        *(float4*)(crow + 4) = *(float4*)&acc[r][4];
    }
}

// ---------------- small GEMM, K=64: C[M,64] = op(A[M,64]) @ B[64,64] + epi ----------------
template<bool PRE, bool ADD, bool BIAS_, bool POST>
__global__ __launch_bounds__(256) void gemm_k64(
    const float* __restrict__ A, const float* __restrict__ B,
    float* __restrict__ C, int M, int N,
    const float* __restrict__ addend, const float* __restrict__ bias,
    const int* __restrict__ predeg, const int* __restrict__ postdeg)
{
    __shared__ float As[32][132];
    __shared__ float Bs[32][64];

    const int tid = threadIdx.x;
    const int row0 = blockIdx.y * 128;
    const int col0 = blockIdx.x * 64;

    float acc[8][4];
#pragma unroll
    for (int r = 0; r < 8; r++)
#pragma unroll
        for (int c = 0; c < 4; c++) acc[r][c] = 0.f;

    const int tm = tid >> 4;
    const int tn = tid & 15;

    for (int ks = 0; ks < 64; ks += 32) {
#pragma unroll
        for (int i = 0; i < 4; i++) {
            int j = tid + i * 256;
            int r = j >> 3;
            int c4 = j & 7;
            int row = row0 + r;
            float4 v = make_float4(0.f, 0.f, 0.f, 0.f);
            if (row < M) {
                v = *(const float4*)(A + (size_t)row * 64 + ks + c4 * 4);
                if (PRE) {
                    float s = rsqrtf(fmaxf((float)predeg[row], 1.0f));
                    v.x *= s; v.y *= s; v.z *= s; v.w *= s;
                }
            }
            As[c4 * 4 + 0][r] = v.x;
            As[c4 * 4 + 1][r] = v.y;
            As[c4 * 4 + 2][r] = v.z;
            As[c4 * 4 + 3][r] = v.w;
        }
#pragma unroll
        for (int i = 0; i < 2; i++) {
            int j = tid + i * 256;
            int r = j >> 4;
            int c4 = j & 15;
            *(float4*)&Bs[r][c4 * 4] =
                *(const float4*)(B + (size_t)(ks + r) * N + col0 + c4 * 4);
        }
        __syncthreads();

#pragma unroll
        for (int k = 0; k < 32; k++) {
            float a[8], b[4];
            *(float4*)&a[0] = *(const float4*)&As[k][tm * 8];
            *(float4*)&a[4] = *(const float4*)&As[k][tm * 8 + 4];
            *(float4*)&b[0] = *(const float4*)&Bs[k][tn * 4];
#pragma unroll
            for (int r = 0; r < 8; r++)
#pragma unroll
                for (int c = 0; c < 4; c++)
                    acc[r][c] = fmaf(a[r], b[c], acc[r][c]);
        }
        __syncthreads();
    }

#pragma unroll
    for (int r = 0; r < 8; r++) {
        int row = row0 + tm * 8 + r;
        if (row >= M) break;
        float ps = 1.f;
        if (POST) ps = rsqrtf(fmaxf((float)postdeg[row], 1.0f));
#pragma unroll
        for (int c = 0; c < 4; c++) {
            int col = col0 + tn * 4 + c;
            float v = acc[r][c];
            if (ADD)   v += addend[(size_t)row * N + col];
            if (BIAS_) v += bias[col];
            if (POST)  v *= ps;
            C[(size_t)row * N + col] = v;
        }
    }
}

// ---------------- gather 1: agg1[dst] = sum_{e in CSR[dst]} xr[src_e, et_e] ----------------
// One warp per dst row; lane -> float2 column. No atomics.
__global__ __launch_bounds__(256) void gather1_kernel(int N) {
    int warp = (blockIdx.x * blockDim.x + threadIdx.x) >> 5;
    int lane = threadIdx.x & 31;
    if (warp >= N) return;
    int start = g_rowstart[warp];
    int end   = g_rowstart[warp + 1];
    const float2* xr2 = (const float2*)g_xr;
    float2 acc = make_float2(0.f, 0.f);
    for (int j = start; j < end; j++) {
        int2 p = g_edge[j];                              // broadcast load
        float2 v = xr2[(size_t)p.x * 256 + p.y * 32 + lane];
        acc.x += v.x; acc.y += v.y;
    }
    ((float2*)g_agg1)[(size_t)warp * 32 + lane] = acc;
}

// ---------------- gather 2: agg2[dst] = sum_{e in CSR[dst]} hs[src_e] ----------------
__global__ __launch_bounds__(256) void gather2_kernel(int N) {
    int warp = (blockIdx.x * blockDim.x + threadIdx.x) >> 5;
    int lane = threadIdx.x & 31;
    if (warp >= N) return;
    int start = g_rowstart[warp];
    int end   = g_rowstart[warp + 1];
    const float2* hs2 = (const float2*)g_hs;
    float2 acc = make_float2(0.f, 0.f);
    for (int j = start; j < end; j++) {
        int2 p = g_edge[j];
        float2 v = hs2[(size_t)p.x * 32 + lane];
        acc.x += v.x; acc.y += v.y;
    }
    ((float2*)g_agg2)[(size_t)warp * 32 + lane] = acc;
}

// ---------------- launch ----------------
extern "C" void kernel_launch(void* const* d_in, const int* in_sizes, int n_in,
                              void* d_out, int out_size) {
    // ---- size-based input discovery (robust to harness input ordering) ----
    const float *X = nullptr, *basis = nullptr, *comp = nullptr;
    const float *loopw = nullptr, *bias1 = nullptr, *w2 = nullptr, *bias2 = nullptr;
    const void  *ei = nullptr, *etA = nullptr, *etB = nullptr;
    int E = EMAX;
    {
        int seen4096 = 0, seen64 = 0;
        long long maxsz = 0;
        for (int i = 0; i < n_in; i++) if (in_sizes[i] > maxsz) maxsz = in_sizes[i];
        for (int i = 0; i < n_in; i++)
            if (in_sizes[i] == maxsz && X == nullptr) X = (const float*)d_in[i];
        long long second = 0;
        for (int i = 0; i < n_in; i++) {
            long long sz = in_sizes[i];
            if (sz < maxsz && sz > second) second = sz;
        }
        E = (int)(second / 2);
        for (int i = 0; i < n_in; i++) {
            long long sz = in_sizes[i];
            const void* p = d_in[i];
            if (sz == maxsz && p == (const void*)X) continue;
            if (sz == second && ei == nullptr) { ei = p; continue; }
            if (sz == (long long)E) {
                if (etA == nullptr) etA = p; else etB = p;
                continue;
            }
            if (sz == 122880) { basis = (const float*)p; continue; }
            if (sz == 240)    { comp  = (const float*)p; continue; }
            if (sz == 4096) {
                if (seen4096 == 0) { loopw = (const float*)p; seen4096 = 1; }
                else               { w2    = (const float*)p; }
                continue;
            }
            if (sz == 64) {
                if (seen64 == 0) { bias1 = (const float*)p; seen64 = 1; }
                else             { bias2 = (const float*)p; }
                continue;
            }
        }
    }
    float* out = (float*)d_out;
    const int N = out_size / H2;   // 50000 output rows

    // Resolve real device addresses of __device__ scratch (host identifiers
    // are shadow symbols; ATS makes misuse silent on GB300).
    void *p_xr_, *p_agg1_, *p_agg2_, *p_hs_, *p_do_, *p_di_, *p_w_;
    cudaGetSymbolAddress(&p_xr_,   g_xr);
    cudaGetSymbolAddress(&p_agg1_, g_agg1);
    cudaGetSymbolAddress(&p_agg2_, g_agg2);
    cudaGetSymbolAddress(&p_hs_,   g_hs);
    cudaGetSymbolAddress(&p_do_,   g_deg_out);
    cudaGetSymbolAddress(&p_di_,   g_deg_in);
    cudaGetSymbolAddress(&p_w_,    g_wrelT);
    float* xr_d     = (float*)p_xr_;
    float* agg1_d   = (float*)p_agg1_;
    float* agg2_d   = (float*)p_agg2_;
    float* hs_d     = (float*)p_hs_;
    int*   degout_d = (int*)p_do_;
    int*   degin_d  = (int*)p_di_;
    float* wrelT_d  = (float*)p_w_;

    detect_kernel<<<1, 1>>>(ei, etA, etB, E, N);
    zero_kernel<<<(N + 255) / 256, 256>>>(N);
    convert_kernel<<<(E + 255) / 256, 256>>>(ei, etA, etB, E, N);

    // CSR build (by dst)
    const int NSB = (N + SCAN_B - 1) / SCAN_B;   // 196 blocks
    scanA_kernel<<<NSB, SCAN_B>>>(N);
    scanB_kernel<<<1, 1024>>>(NSB);
    scanC_kernel<<<NSB, SCAN_B>>>(N, E);
    fill_kernel<<<(E + 255) / 256, 256>>>(E);

    wrel_kernel<<<(64 * 512 + 255) / 256, 256>>>(comp, basis);

    const int MY = (N + 127) / 128;

    // xr = X @ WrelT : [N,64] @ [64,512]
    gemm_xr<<<dim3(4, MY), 256>>>(X, wrelT_d, xr_d, N);

    // agg1[dst] = sum xr[src, etype]   (CSR gather, no atomics)
    gather1_kernel<<<(N * 32 + 255) / 256, 256>>>(N);

    // hs = (agg1 + X @ loopw + bias1) * rsqrt(max(deg_out,1))
    gemm_k64<false, true, true, true><<<dim3(1, MY), 256>>>(
        X, loopw, hs_d, N, 64, agg1_d, bias1, nullptr, degout_d);

    // agg2[dst] = sum hs[src]          (CSR gather, no atomics)
    gather2_kernel<<<(N * 32 + 255) / 256, 256>>>(N);

    // out = (agg2 * rsqrt(max(deg_in,1))) @ w2 + bias2
    gemm_k64<true, false, true, false><<<dim3(1, MY), 256>>>(
        agg2_d, w2, out, N, 64, nullptr, bias2, degin_d, nullptr);
}

// round 15
// speedup vs baseline: 1.3234x; 1.3234x over previous
#include <cuda_runtime.h>
#include <cstdint>

// Problem constants (shapes fixed by the dataset)
#define NMAX 50000
#define EMAX 1000000
#define DIN 64
#define H1 64
#define H2 64
#define RNUM 8
#define BNUM 30

// ---------------- device scratch (static: no allocs allowed) ----------------
__device__ float4 g_xr[(size_t)NMAX * 512 / 4];    // [N, R*H1] = [N,512]  ~102MB
__device__ float4 g_agg1[(size_t)NMAX * 64 / 4];   // RGCN aggregation
__device__ float4 g_agg2[(size_t)NMAX * 64 / 4];   // GraphConv aggregation
__device__ float4 g_hs[(size_t)NMAX * 64 / 4];     // h * rsqrt(deg_out)
__device__ int    g_deg_out[NMAX];
__device__ int    g_deg_in[NMAX];
__device__ float  g_wrelT[64 * 512];               // [k][r*64+o]
__device__ int    g_src[EMAX];
__device__ int    g_dst[EMAX];
__device__ int    g_et [EMAX];
__device__ int    g_ei_is64;
__device__ int    g_et_sel;
__device__ int    g_et_is64;

// vectorized global reduction (sm_90+): 1 lane-op moves 16B
__device__ __forceinline__ void red_add_v4(float* addr, float4 v) {
    asm volatile("red.global.add.v4.f32 [%0], {%1, %2, %3, %4};"
                 :: "l"(addr), "f"(v.x), "f"(v.y), "f"(v.z), "f"(v.w)
                 : "memory");
}

// ---------------- dtype + identity detection (parallel: 1 warp per probe) ----------------
// Probe w checks 64 samples, 2 per lane; ballot-combined. Replaces the serial
// 1-thread version (up to ~5*64 dependent DRAM loads ~ tens of us).
__global__ void detect_kernel(const void* ei, const void* etA, const void* etB,
                              int E, int N) {
    __shared__ int ok[5];
    int w = threadIdx.x >> 5;
    int lane = threadIdx.x & 31;
    if (w < 5) {
        // probe configs: {ptr, cnt, hi, is64}
        const void* p = (w == 0) ? ei : (w <= 2 ? etA : etB);
        int is64 = (w == 0) || (w == 2) || (w == 4);
        int cnt  = (w == 0) ? E : ((w == 2 || w == 4) ? E / 2 : E);
        long long hi = (w == 0) ? (long long)N : 64;
        int myok = 1;
        for (int i = lane; i < 64; i += 32) {
            int stride = cnt > 64 ? cnt / 64 : 1;
            int idx = i * stride;
            if (idx < cnt) {
                long long v = is64 ? ((const long long*)p)[idx]
                                   : (long long)((const int*)p)[idx];
                if (v < 0 || v >= hi) myok = 0;
            }
        }
        unsigned m = __ballot_sync(0xFFFFFFFFu, myok);
        if (lane == 0) ok[w] = (m == 0xFFFFFFFFu);
    }
    __syncthreads();
    if (threadIdx.x == 0) {
        int A32 = ok[1], A64 = ok[2], B32 = ok[3], B64 = ok[4];
        g_ei_is64 = ok[0];
        int selA = (A32 || A64);
        int selB = (B32 || B64);
        if (selA && !selB)      { g_et_sel = 0; g_et_is64 = A64; }
        else if (selB && !selA) { g_et_sel = 1; g_et_is64 = B64; }
        else                    { g_et_sel = 1; g_et_is64 = B64; }
    }
}

// ---------------- zero scratch ----------------
__global__ void zero_kernel(int n) {
    int i = blockIdx.x * blockDim.x + threadIdx.x;
    float4 z = make_float4(0.f, 0.f, 0.f, 0.f);
    int nf4 = n * 16;
    if (i < nf4) { g_agg1[i] = z; g_agg2[i] = z; }
    if (i < n)   { g_deg_out[i] = 0; g_deg_in[i] = 0; }
}

// ---------------- convert indices + degree counts (clamped: no traps) ----------------
__global__ void convert_kernel(const void* ei, const void* etA, const void* etB,
                               int E, int N) {
    int e = blockIdx.x * blockDim.x + threadIdx.x;
    if (e >= E) return;
    const void* et = g_et_sel ? etB : etA;
    long long s, d, r;
    if (g_ei_is64) {
        s = ((const long long*)ei)[e];
        d = ((const long long*)ei)[E + e];
    } else {
        s = ((const int*)ei)[e];
        d = ((const int*)ei)[E + e];
    }
    if (g_et_is64) r = ((const long long*)et)[e];
    else           r = ((const int*)et)[e];
    int si = (int)s, di = (int)d, ri = (int)r;
    if (si < 0) si = 0; if (si >= N) si = N - 1;
    if (di < 0) di = 0; if (di >= N) di = N - 1;
    ri &= 7;
    g_src[e] = si; g_dst[e] = di; g_et[e] = ri;
    atomicAdd(&g_deg_out[si], 1);
    atomicAdd(&g_deg_in[di], 1);
}

// ---------------- Wrel^T, stored [k][r*64+o] ----------------
__global__ void wrel_kernel(const float* __restrict__ comp,
                            const float* __restrict__ basis) {
    int idx = blockIdx.x * blockDim.x + threadIdx.x;
    if (idx >= 64 * 512) return;
    int k = idx >> 9;
    int rem = idx & 511;
    int r = rem >> 6;
    int o = rem & 63;
    float s = 0.f;
#pragma unroll
    for (int b = 0; b < BNUM; b++)
        s = fmaf(comp[r * BNUM + b], basis[b * (DIN * H1) + k * H1 + o], s);
    g_wrelT[idx] = s;
}

// ---------------- big GEMM (xr): C[M,512] = A[M,64] @ B[64,512] ----------------
// Tile 128x128, 256 threads, 8x8 microtile, K slabs of 32.
__global__ __launch_bounds__(256) void gemm_xr(
    const float* __restrict__ A, const float* __restrict__ B,
    float* __restrict__ C, int M)
{
    __shared__ float As[32][132];
    __shared__ float Bs[32][128];

    const int tid = threadIdx.x;
    const int row0 = blockIdx.y * 128;
    const int col0 = blockIdx.x * 128;

    float acc[8][8];
#pragma unroll
    for (int r = 0; r < 8; r++)
#pragma unroll
        for (int c = 0; c < 8; c++) acc[r][c] = 0.f;

    const int tm = tid >> 4;
    const int tn = tid & 15;

    for (int ks = 0; ks < 64; ks += 32) {
#pragma unroll
        for (int i = 0; i < 4; i++) {
            int j = tid + i * 256;
            int r = j >> 3;
            int c4 = j & 7;
            int row = row0 + r;
            float4 v = make_float4(0.f, 0.f, 0.f, 0.f);
            if (row < M)
                v = *(const float4*)(A + (size_t)row * 64 + ks + c4 * 4);
            As[c4 * 4 + 0][r] = v.x;
            As[c4 * 4 + 1][r] = v.y;
            As[c4 * 4 + 2][r] = v.z;
            As[c4 * 4 + 3][r] = v.w;
        }
#pragma unroll
        for (int i = 0; i < 4; i++) {
            int j = tid + i * 256;
            int r = j >> 5;
            int c4 = j & 31;
            *(float4*)&Bs[r][c4 * 4] =
                *(const float4*)(B + (size_t)(ks + r) * 512 + col0 + c4 * 4);
        }
        __syncthreads();

#pragma unroll
        for (int k = 0; k < 32; k++) {
            float a[8], b[8];
            *(float4*)&a[0] = *(const float4*)&As[k][tm * 8];
            *(float4*)&a[4] = *(const float4*)&As[k][tm * 8 + 4];
            *(float4*)&b[0] = *(const float4*)&Bs[k][tn * 8];
            *(float4*)&b[4] = *(const float4*)&Bs[k][tn * 8 + 4];
#pragma unroll
            for (int r = 0; r < 8; r++)
#pragma unroll
                for (int c = 0; c < 8; c++)
                    acc[r][c] = fmaf(a[r], b[c], acc[r][c]);
        }
        __syncthreads();
    }

#pragma unroll
    for (int r = 0; r < 8; r++) {
        int row = row0 + tm * 8 + r;
        if (row >= M) break;
        float* crow = C + (size_t)row * 512 + col0 + tn * 8;
        *(float4*)(crow)     = *(float4*)&acc[r][0];
        *(float4*)(crow + 4) = *(float4*)&acc[r][4];
    }
}

// ---------------- small GEMM, K=64: C[M,64] = op(A[M,64]) @ B[64,64] + epi ----------------
template<bool PRE, bool ADD, bool BIAS_, bool POST>
__global__ __launch_bounds__(256) void gemm_k64(
    const float* __restrict__ A, const float* __restrict__ B,
    float* __restrict__ C, int M, int N,
    const float* __restrict__ addend, const float* __restrict__ bias,
    const int* __restrict__ predeg, const int* __restrict__ postdeg)
{
    __shared__ float As[32][132];
    __shared__ float Bs[32][64];

    const int tid = threadIdx.x;
    const int row0 = blockIdx.y * 128;
    const int col0 = blockIdx.x * 64;

    float acc[8][4];
#pragma unroll
    for (int r = 0; r < 8; r++)
#pragma unroll
        for (int c = 0; c < 4; c++) acc[r][c] = 0.f;

    const int tm = tid >> 4;
    const int tn = tid & 15;

    for (int ks = 0; ks < 64; ks += 32) {
#pragma unroll
        for (int i = 0; i < 4; i++) {
            int j = tid + i * 256;
            int r = j >> 3;
            int c4 = j & 7;
            int row = row0 + r;
            float4 v = make_float4(0.f, 0.f, 0.f, 0.f);
            if (row < M) {
                v = *(const float4*)(A + (size_t)row * 64 + ks + c4 * 4);
                if (PRE) {
                    float s = rsqrtf(fmaxf((float)predeg[row], 1.0f));
                    v.x *= s; v.y *= s; v.z *= s; v.w *= s;
                }
            }
            As[c4 * 4 + 0][r] = v.x;
            As[c4 * 4 + 1][r] = v.y;
            As[c4 * 4 + 2][r] = v.z;
            As[c4 * 4 + 3][r] = v.w;
        }
#pragma unroll
        for (int i = 0; i < 2; i++) {
            int j = tid + i * 256;
            int r = j >> 4;
            int c4 = j & 15;
            *(float4*)&Bs[r][c4 * 4] =
                *(const float4*)(B + (size_t)(ks + r) * N + col0 + c4 * 4);
        }
        __syncthreads();

#pragma unroll
        for (int k = 0; k < 32; k++) {
            float a[8], b[4];
            *(float4*)&a[0] = *(const float4*)&As[k][tm * 8];
            *(float4*)&a[4] = *(const float4*)&As[k][tm * 8 + 4];
            *(float4*)&b[0] = *(const float4*)&Bs[k][tn * 4];
#pragma unroll
            for (int r = 0; r < 8; r++)
#pragma unroll
                for (int c = 0; c < 4; c++)
                    acc[r][c] = fmaf(a[r], b[c], acc[r][c]);
        }
        __syncthreads();
    }

#pragma unroll
    for (int r = 0; r < 8; r++) {
        int row = row0 + tm * 8 + r;
        if (row >= M) break;
        float ps = 1.f;
        if (POST) ps = rsqrtf(fmaxf((float)postdeg[row], 1.0f));
#pragma unroll
        for (int c = 0; c < 4; c++) {
            int col = col0 + tn * 4 + c;
            float v = acc[r][c];
            if (ADD)   v += addend[(size_t)row * N + col];
            if (BIAS_) v += bias[col];
            if (POST)  v *= ps;
            C[(size_t)row * N + col] = v;
        }
    }
}

// ---------------- scatter 1: agg1[dst] += xr[src, etype]  (v4 red) ----------------
__global__ void scatter1_kernel(int E) {
    int i = blockIdx.x * blockDim.x + threadIdx.x;
    if (i >= E * 16) return;
    int e = i >> 4;
    int q = i & 15;
    int s = g_src[e];
    int d = g_dst[e];
    int r = g_et[e];
    float4 v = g_xr[(size_t)s * 128 + r * 16 + q];
    red_add_v4((float*)g_agg1 + (size_t)d * 64 + q * 4, v);
}

// ---------------- scatter 2: agg2[dst] += hs[src]  (v4 red) ----------------
__global__ void scatter2_kernel(int E) {
    int i = blockIdx.x * blockDim.x + threadIdx.x;
    if (i >= E * 16) return;
    int e = i >> 4;
    int q = i & 15;
    int s = g_src[e];
    int d = g_dst[e];
    float4 v = g_hs[(size_t)s * 16 + q];
    red_add_v4((float*)g_agg2 + (size_t)d * 64 + q * 4, v);
}

// ---------------- launch ----------------
extern "C" void kernel_launch(void* const* d_in, const int* in_sizes, int n_in,
                              void* d_out, int out_size) {
    // ---- size-based input discovery (robust to harness input ordering) ----
    const float *X = nullptr, *basis = nullptr, *comp = nullptr;
    const float *loopw = nullptr, *bias1 = nullptr, *w2 = nullptr, *bias2 = nullptr;
    const void  *ei = nullptr, *etA = nullptr, *etB = nullptr;
    int E = EMAX;
    {
        int seen4096 = 0, seen64 = 0;
        long long maxsz = 0;
        for (int i = 0; i < n_in; i++) if (in_sizes[i] > maxsz) maxsz = in_sizes[i];
        for (int i = 0; i < n_in; i++)
            if (in_sizes[i] == maxsz && X == nullptr) X = (const float*)d_in[i];
        long long second = 0;
        for (int i = 0; i < n_in; i++) {
            long long sz = in_sizes[i];
            if (sz < maxsz && sz > second) second = sz;
        }
        E = (int)(second / 2);
        for (int i = 0; i < n_in; i++) {
            long long sz = in_sizes[i];
            const void* p = d_in[i];
            if (sz == maxsz && p == (const void*)X) continue;
            if (sz == second && ei == nullptr) { ei = p; continue; }
            if (sz == (long long)E) {
                if (etA == nullptr) etA = p; else etB = p;
                continue;
            }
            if (sz == 122880) { basis = (const float*)p; continue; }
            if (sz == 240)    { comp  = (const float*)p; continue; }
            if (sz == 4096) {
                if (seen4096 == 0) { loopw = (const float*)p; seen4096 = 1; }
                else               { w2    = (const float*)p; }
                continue;
            }
            if (sz == 64) {
                if (seen64 == 0) { bias1 = (const float*)p; seen64 = 1; }
                else             { bias2 = (const float*)p; }
                continue;
            }
        }
    }
    float* out = (float*)d_out;
    const int N = out_size / H2;   // 50000 output rows

    // Resolve real device addresses of __device__ scratch (host identifiers
    // are shadow symbols; ATS makes misuse silent on GB300).
    void *p_xr_, *p_agg1_, *p_agg2_, *p_hs_, *p_do_, *p_di_, *p_w_;
    cudaGetSymbolAddress(&p_xr_,   g_xr);
    cudaGetSymbolAddress(&p_agg1_, g_agg1);
    cudaGetSymbolAddress(&p_agg2_, g_agg2);
    cudaGetSymbolAddress(&p_hs_,   g_hs);
    cudaGetSymbolAddress(&p_do_,   g_deg_out);
    cudaGetSymbolAddress(&p_di_,   g_deg_in);
    cudaGetSymbolAddress(&p_w_,    g_wrelT);
    float* xr_d     = (float*)p_xr_;
    float* agg1_d   = (float*)p_agg1_;
    float* agg2_d   = (float*)p_agg2_;
    float* hs_d     = (float*)p_hs_;
    int*   degout_d = (int*)p_do_;
    int*   degin_d  = (int*)p_di_;
    float* wrelT_d  = (float*)p_w_;

    detect_kernel<<<1, 160>>>(ei, etA, etB, E, N);

    const int ZB = (N * 16 + 255) / 256;
    zero_kernel<<<ZB, 256>>>(N);

    convert_kernel<<<(E + 255) / 256, 256>>>(ei, etA, etB, E, N);
    wrel_kernel<<<(64 * 512 + 255) / 256, 256>>>(comp, basis);

    const int MY = (N + 127) / 128;

    // xr = X @ WrelT : [N,64] @ [64,512]  (128x128 tiles, 8x8 microtile)
    gemm_xr<<<dim3(4, MY), 256>>>(X, wrelT_d, xr_d, N);

    // agg1[dst] += xr[src, etype]
    scatter1_kernel<<<(E * 16 + 255) / 256, 256>>>(E);

    // hs = (agg1 + X @ loopw + bias1) * rsqrt(max(deg_out,1))
    gemm_k64<false, true, true, true><<<dim3(1, MY), 256>>>(
        X, loopw, hs_d, N, 64, agg1_d, bias1, nullptr, degout_d);

    // agg2[dst] += hs[src]
    scatter2_kernel<<<(E * 16 + 255) / 256, 256>>>(E);

    // out = (agg2 * rsqrt(max(deg_in,1))) @ w2 + bias2
    gemm_k64<true, false, true, false><<<dim3(1, MY), 256>>>(
        agg2_d, w2, out, N, 64, nullptr, bias2, degin_d, nullptr);
}

// round 16
// speedup vs baseline: 1.4471x; 1.0935x over previous
#include <cuda_runtime.h>
#include <cstdint>

#define NMAX 50000
#define EMAX 1000000
#define DIN 64
#define H1 64
#define H2 64
#define RNUM 8
#define BNUM 30

// ---------------- device scratch ----------------
__device__ float4 g_xr[(size_t)NMAX * 512 / 4];
__device__ float4 g_agg1[(size_t)NMAX * 64 / 4];
__device__ float4 g_agg2[(size_t)NMAX * 64 / 4];
__device__ float4 g_hs[(size_t)NMAX * 64 / 4];
__device__ int    g_deg_out[NMAX];
__device__ int    g_deg_in[NMAX];
__device__ float  g_wrelH[64 * 512];   // tf32(hi) of WrelT, [k][r*64+o]
__device__ float  g_wrelL[64 * 512];   // tf32(lo)
__device__ int    g_src[EMAX];
__device__ int    g_dst[EMAX];
__device__ int    g_et [EMAX];
__device__ int    g_ei_is64;
__device__ int    g_et_sel;
__device__ int    g_et_is64;

__device__ __forceinline__ void red_add_v4(float* addr, float4 v) {
    asm volatile("red.global.add.v4.f32 [%0], {%1, %2, %3, %4};"
                 :: "l"(addr), "f"(v.x), "f"(v.y), "f"(v.z), "f"(v.w)
                 : "memory");
}

__device__ __forceinline__ void split_tf32(float v, uint32_t& h, uint32_t& l) {
    uint32_t hb;
    asm("cvt.rna.tf32.f32 %0, %1;" : "=r"(hb) : "f"(v));
    float r = v - __uint_as_float(hb);
    uint32_t lb;
    asm("cvt.rna.tf32.f32 %0, %1;" : "=r"(lb) : "f"(r));
    h = hb; l = lb;
}

#define MMA_TF32(d, a, b)                                                     \
    asm volatile(                                                             \
        "mma.sync.aligned.m16n8k8.row.col.f32.tf32.tf32.f32 "                \
        "{%0,%1,%2,%3}, {%4,%5,%6,%7}, {%8,%9}, {%0,%1,%2,%3};"              \
        : "+f"((d)[0]), "+f"((d)[1]), "+f"((d)[2]), "+f"((d)[3])              \
        : "r"((a)[0]), "r"((a)[1]), "r"((a)[2]), "r"((a)[3]),                 \
          "r"((b)[0]), "r"((b)[1]))

// ---------------- dtype + identity detection (1 warp per probe) ----------------
__global__ void detect_kernel(const void* ei, const void* etA, const void* etB,
                              int E, int N) {
    __shared__ int ok[5];
    int w = threadIdx.x >> 5;
    int lane = threadIdx.x & 31;
    if (w < 5) {
        const void* p = (w == 0) ? ei : (w <= 2 ? etA : etB);
        int is64 = (w == 0) || (w == 2) || (w == 4);
        int cnt  = (w == 0) ? E : ((w == 2 || w == 4) ? E / 2 : E);
        long long hi = (w == 0) ? (long long)N : 64;
        int myok = 1;
        for (int i = lane; i < 64; i += 32) {
            int stride = cnt > 64 ? cnt / 64 : 1;
            int idx = i * stride;
            if (idx < cnt) {
                long long v = is64 ? ((const long long*)p)[idx]
                                   : (long long)((const int*)p)[idx];
                if (v < 0 || v >= hi) myok = 0;
            }
        }
        unsigned m = __ballot_sync(0xFFFFFFFFu, myok);
        if (lane == 0) ok[w] = (m == 0xFFFFFFFFu);
    }
    __syncthreads();
    if (threadIdx.x == 0) {
        int A32 = ok[1], A64 = ok[2], B32 = ok[3], B64 = ok[4];
        g_ei_is64 = ok[0];
        int selA = (A32 || A64);
        int selB = (B32 || B64);
        if (selA && !selB)      { g_et_sel = 0; g_et_is64 = A64; }
        else if (selB && !selA) { g_et_sel = 1; g_et_is64 = B64; }
        else                    { g_et_sel = 1; g_et_is64 = B64; }
    }
}

// ---------------- zero scratch ----------------
__global__ void zero_kernel(int n) {
    int i = blockIdx.x * blockDim.x + threadIdx.x;
    float4 z = make_float4(0.f, 0.f, 0.f, 0.f);
    int nf4 = n * 16;
    if (i < nf4) { g_agg1[i] = z; g_agg2[i] = z; }
    if (i < n)   { g_deg_out[i] = 0; g_deg_in[i] = 0; }
}

// ---------------- convert indices + degree counts ----------------
__global__ void convert_kernel(const void* ei, const void* etA, const void* etB,
                               int E, int N) {
    int e = blockIdx.x * blockDim.x + threadIdx.x;
    if (e >= E) return;
    const void* et = g_et_sel ? etB : etA;
    long long s, d, r;
    if (g_ei_is64) {
        s = ((const long long*)ei)[e];
        d = ((const long long*)ei)[E + e];
    } else {
        s = ((const int*)ei)[e];
        d = ((const int*)ei)[E + e];
    }
    if (g_et_is64) r = ((const long long*)et)[e];
    else           r = ((const int*)et)[e];
    int si = (int)s, di = (int)d, ri = (int)r;
    if (si < 0) si = 0; if (si >= N) si = N - 1;
    if (di < 0) di = 0; if (di >= N) di = N - 1;
    ri &= 7;
    g_src[e] = si; g_dst[e] = di; g_et[e] = ri;
    atomicAdd(&g_deg_out[si], 1);
    atomicAdd(&g_deg_in[di], 1);
}

// ---------------- Wrel^T (exact fp32) -> tf32 hi/lo pair ----------------
__global__ void wrel_kernel(const float* __restrict__ comp,
                            const float* __restrict__ basis) {
    int idx = blockIdx.x * blockDim.x + threadIdx.x;
    if (idx >= 64 * 512) return;
    int k = idx >> 9;
    int rem = idx & 511;
    int r = rem >> 6;
    int o = rem & 63;
    float s = 0.f;
#pragma unroll
    for (int b = 0; b < BNUM; b++)
        s = fmaf(comp[r * BNUM + b], basis[b * (DIN * H1) + k * H1 + o], s);
    uint32_t h, l;
    split_tf32(s, h, l);
    g_wrelH[idx] = __uint_as_float(h);
    g_wrelL[idx] = __uint_as_float(l);
}

// ---------------- tensor-core GEMM (xr): C[M,512] = A[M,64] @ W[64,512] ----------------
// CTA 128x128, 8 warps (4x2), warp tile 32x64, split-tf32 (3 mma per tile-kstep).
#define AS_STRIDE 68
#define BS_STRIDE 136
__global__ __launch_bounds__(256) void gemm_xr_tc(
    const float* __restrict__ A, const float* __restrict__ Bh,
    const float* __restrict__ Bl, float* __restrict__ C, int M)
{
    extern __shared__ float sm[];
    float* As  = sm;                         // [128][68]
    float* Bhs = sm + 128 * AS_STRIDE;       // [64][136]
    float* Bls = Bhs + 64 * BS_STRIDE;       // [64][136]

    const int tid  = threadIdx.x;
    const int warp = tid >> 5;
    const int lane = tid & 31;
    const int g    = lane >> 2;       // groupID 0..7
    const int tig  = lane & 3;        // thread-in-group 0..3
    const int row0 = blockIdx.y * 128;
    const int col0 = blockIdx.x * 128;

    // load A tile (128x64 fp32), zero-fill OOB rows
#pragma unroll
    for (int i = 0; i < 8; i++) {
        int j = tid + i * 256;
        int r = j >> 4;          // 16 float4 per row
        int c4 = j & 15;
        int row = row0 + r;
        float4 v = make_float4(0.f, 0.f, 0.f, 0.f);
        if (row < M) v = *(const float4*)(A + (size_t)row * 64 + c4 * 4);
        *(float4*)&As[r * AS_STRIDE + c4 * 4] = v;
    }
    // load B hi/lo tiles (64x128)
#pragma unroll
    for (int i = 0; i < 8; i++) {
        int j = tid + i * 256;
        int k = j >> 5;          // 32 float4 per row
        int c4 = j & 31;
        *(float4*)&Bhs[k * BS_STRIDE + c4 * 4] =
            *(const float4*)(Bh + (size_t)k * 512 + col0 + c4 * 4);
        *(float4*)&Bls[k * BS_STRIDE + c4 * 4] =
            *(const float4*)(Bl + (size_t)k * 512 + col0 + c4 * 4);
    }
    __syncthreads();

    const int m0 = (warp & 3) * 32;
    const int n0 = (warp >> 2) * 64;

    float d[2][8][4];
#pragma unroll
    for (int mf = 0; mf < 2; mf++)
#pragma unroll
        for (int nf = 0; nf < 8; nf++)
#pragma unroll
            for (int q = 0; q < 4; q++) d[mf][nf][q] = 0.f;

#pragma unroll
    for (int ks = 0; ks < 64; ks += 8) {
        uint32_t ah[2][4], al[2][4];
#pragma unroll
        for (int mf = 0; mf < 2; mf++) {
            int rm = m0 + mf * 16 + g;
            float v0 = As[(rm)     * AS_STRIDE + ks + tig];
            float v1 = As[(rm + 8) * AS_STRIDE + ks + tig];
            float v2 = As[(rm)     * AS_STRIDE + ks + tig + 4];
            float v3 = As[(rm + 8) * AS_STRIDE + ks + tig + 4];
            split_tf32(v0, ah[mf][0], al[mf][0]);
            split_tf32(v1, ah[mf][1], al[mf][1]);
            split_tf32(v2, ah[mf][2], al[mf][2]);
            split_tf32(v3, ah[mf][3], al[mf][3]);
        }
        uint32_t bhf[8][2], blf[8][2];
#pragma unroll
        for (int nf = 0; nf < 8; nf++) {
            int c = n0 + nf * 8 + g;
            bhf[nf][0] = __float_as_uint(Bhs[(ks + tig)     * BS_STRIDE + c]);
            bhf[nf][1] = __float_as_uint(Bhs[(ks + tig + 4) * BS_STRIDE + c]);
            blf[nf][0] = __float_as_uint(Bls[(ks + tig)     * BS_STRIDE + c]);
            blf[nf][1] = __float_as_uint(Bls[(ks + tig + 4) * BS_STRIDE + c]);
        }
#pragma unroll
        for (int mf = 0; mf < 2; mf++)
#pragma unroll
            for (int nf = 0; nf < 8; nf++) {
                MMA_TF32(d[mf][nf], ah[mf], bhf[nf]);
                MMA_TF32(d[mf][nf], al[mf], bhf[nf]);
                MMA_TF32(d[mf][nf], ah[mf], blf[nf]);
            }
    }

    // epilogue
#pragma unroll
    for (int mf = 0; mf < 2; mf++) {
        int r0 = row0 + m0 + mf * 16 + g;
        int r1 = r0 + 8;
#pragma unroll
        for (int nf = 0; nf < 8; nf++) {
            int c = col0 + n0 + nf * 8 + 2 * tig;
            if (r0 < M)
                *(float2*)(C + (size_t)r0 * 512 + c) =
                    make_float2(d[mf][nf][0], d[mf][nf][1]);
            if (r1 < M)
                *(float2*)(C + (size_t)r1 * 512 + c) =
                    make_float2(d[mf][nf][2], d[mf][nf][3]);
        }
    }
}
#define GEMM_XR_SMEM ((128 * AS_STRIDE + 2 * 64 * BS_STRIDE) * 4)

// ---------------- small GEMM, K=64: C[M,64] = op(A[M,64]) @ B[64,64] + epi ----------------
template<bool PRE, bool ADD, bool BIAS_, bool POST>
__global__ __launch_bounds__(256) void gemm_k64(
    const float* __restrict__ A, const float* __restrict__ B,
    float* __restrict__ C, int M, int N,
    const float* __restrict__ addend, const float* __restrict__ bias,
    const int* __restrict__ predeg, const int* __restrict__ postdeg)
{
    __shared__ float As[32][132];
    __shared__ float Bs[32][64];

    const int tid = threadIdx.x;
    const int row0 = blockIdx.y * 128;
    const int col0 = blockIdx.x * 64;

    float acc[8][4];
#pragma unroll
    for (int r = 0; r < 8; r++)
#pragma unroll
        for (int c = 0; c < 4; c++) acc[r][c] = 0.f;

    const int tm = tid >> 4;
    const int tn = tid & 15;

    for (int ks = 0; ks < 64; ks += 32) {
#pragma unroll
        for (int i = 0; i < 4; i++) {
            int j = tid + i * 256;
            int r = j >> 3;
            int c4 = j & 7;
            int row = row0 + r;
            float4 v = make_float4(0.f, 0.f, 0.f, 0.f);
            if (row < M) {
                v = *(const float4*)(A + (size_t)row * 64 + ks + c4 * 4);
                if (PRE) {
                    float s = rsqrtf(fmaxf((float)predeg[row], 1.0f));
                    v.x *= s; v.y *= s; v.z *= s; v.w *= s;
                }
            }
            As[c4 * 4 + 0][r] = v.x;
            As[c4 * 4 + 1][r] = v.y;
            As[c4 * 4 + 2][r] = v.z;
            As[c4 * 4 + 3][r] = v.w;
        }
#pragma unroll
        for (int i = 0; i < 2; i++) {
            int j = tid + i * 256;
            int r = j >> 4;
            int c4 = j & 15;
            *(float4*)&Bs[r][c4 * 4] =
                *(const float4*)(B + (size_t)(ks + r) * N + col0 + c4 * 4);
        }
        __syncthreads();

#pragma unroll
        for (int k = 0; k < 32; k++) {
            float a[8], b[4];
            *(float4*)&a[0] = *(const float4*)&As[k][tm * 8];
            *(float4*)&a[4] = *(const float4*)&As[k][tm * 8 + 4];
            *(float4*)&b[0] = *(const float4*)&Bs[k][tn * 4];
#pragma unroll
            for (int r = 0; r < 8; r++)
#pragma unroll
                for (int c = 0; c < 4; c++)
                    acc[r][c] = fmaf(a[r], b[c], acc[r][c]);
        }
        __syncthreads();
    }

#pragma unroll
    for (int r = 0; r < 8; r++) {
        int row = row0 + tm * 8 + r;
        if (row >= M) break;
        float ps = 1.f;
        if (POST) ps = rsqrtf(fmaxf((float)postdeg[row], 1.0f));
#pragma unroll
        for (int c = 0; c < 4; c++) {
            int col = col0 + tn * 4 + c;
            float v = acc[r][c];
            if (ADD)   v += addend[(size_t)row * N + col];
            if (BIAS_) v += bias[col];
            if (POST)  v *= ps;
            C[(size_t)row * N + col] = v;
        }
    }
}

// ---------------- scatter 1: agg1[dst] += xr[src, etype]  (v4 red) ----------------
__global__ void scatter1_kernel(int E) {
    int i = blockIdx.x * blockDim.x + threadIdx.x;
    if (i >= E * 16) return;
    int e = i >> 4;
    int q = i & 15;
    int s = g_src[e];
    int d = g_dst[e];
    int r = g_et[e];
    float4 v = g_xr[(size_t)s * 128 + r * 16 + q];
    red_add_v4((float*)g_agg1 + (size_t)d * 64 + q * 4, v);
}

// ---------------- scatter 2: agg2[dst] += hs[src]  (v4 red) ----------------
__global__ void scatter2_kernel(int E) {
    int i = blockIdx.x * blockDim.x + threadIdx.x;
    if (i >= E * 16) return;
    int e = i >> 4;
    int q = i & 15;
    int s = g_src[e];
    int d = g_dst[e];
    float4 v = g_hs[(size_t)s * 16 + q];
    red_add_v4((float*)g_agg2 + (size_t)d * 64 + q * 4, v);
}

// ---------------- launch ----------------
extern "C" void kernel_launch(void* const* d_in, const int* in_sizes, int n_in,
                              void* d_out, int out_size) {
    const float *X = nullptr, *basis = nullptr, *comp = nullptr;
    const float *loopw = nullptr, *bias1 = nullptr, *w2 = nullptr, *bias2 = nullptr;
    const void  *ei = nullptr, *etA = nullptr, *etB = nullptr;
    int E = EMAX;
    {
        int seen4096 = 0, seen64 = 0;
        long long maxsz = 0;
        for (int i = 0; i < n_in; i++) if (in_sizes[i] > maxsz) maxsz = in_sizes[i];
        for (int i = 0; i < n_in; i++)
            if (in_sizes[i] == maxsz && X == nullptr) X = (const float*)d_in[i];
        long long second = 0;
        for (int i = 0; i < n_in; i++) {
            long long sz = in_sizes[i];
            if (sz < maxsz && sz > second) second = sz;
        }
        E = (int)(second / 2);
        for (int i = 0; i < n_in; i++) {
            long long sz = in_sizes[i];
            const void* p = d_in[i];
            if (sz == maxsz && p == (const void*)X) continue;
            if (sz == second && ei == nullptr) { ei = p; continue; }
            if (sz == (long long)E) {
                if (etA == nullptr) etA = p; else etB = p;
                continue;
            }
            if (sz == 122880) { basis = (const float*)p; continue; }
            if (sz == 240)    { comp  = (const float*)p; continue; }
            if (sz == 4096) {
                if (seen4096 == 0) { loopw = (const float*)p; seen4096 = 1; }
                else               { w2    = (const float*)p; }
                continue;
            }
            if (sz == 64) {
                if (seen64 == 0) { bias1 = (const float*)p; seen64 = 1; }
                else             { bias2 = (const float*)p; }
                continue;
            }
        }
    }
    float* out = (float*)d_out;
    const int N = out_size / H2;

    // real device addresses of __device__ scratch (host identifiers are shadows)
    void *p_xr_, *p_agg1_, *p_agg2_, *p_hs_, *p_do_, *p_di_, *p_wh_, *p_wl_;
    cudaGetSymbolAddress(&p_xr_,   g_xr);
    cudaGetSymbolAddress(&p_agg1_, g_agg1);
    cudaGetSymbolAddress(&p_agg2_, g_agg2);
    cudaGetSymbolAddress(&p_hs_,   g_hs);
    cudaGetSymbolAddress(&p_do_,   g_deg_out);
    cudaGetSymbolAddress(&p_di_,   g_deg_in);
    cudaGetSymbolAddress(&p_wh_,   g_wrelH);
    cudaGetSymbolAddress(&p_wl_,   g_wrelL);
    float* xr_d     = (float*)p_xr_;
    float* agg1_d   = (float*)p_agg1_;
    float* agg2_d   = (float*)p_agg2_;
    float* hs_d     = (float*)p_hs_;
    int*   degout_d = (int*)p_do_;
    int*   degin_d  = (int*)p_di_;
    float* wrelH_d  = (float*)p_wh_;
    float* wrelL_d  = (float*)p_wl_;

    detect_kernel<<<1, 160>>>(ei, etA, etB, E, N);

    const int ZB = (N * 16 + 255) / 256;
    zero_kernel<<<ZB, 256>>>(N);

    convert_kernel<<<(E + 255) / 256, 256>>>(ei, etA, etB, E, N);
    wrel_kernel<<<(64 * 512 + 255) / 256, 256>>>(comp, basis);

    const int MY = (N + 127) / 128;

    // xr = X @ Wrel : tensor-core split-tf32
    cudaFuncSetAttribute(gemm_xr_tc, cudaFuncAttributeMaxDynamicSharedMemorySize,
                         GEMM_XR_SMEM);
    gemm_xr_tc<<<dim3(4, MY), 256, GEMM_XR_SMEM>>>(X, wrelH_d, wrelL_d, xr_d, N);

    // agg1[dst] += xr[src, etype]
    scatter1_kernel<<<(E * 16 + 255) / 256, 256>>>(E);

    // hs = (agg1 + X @ loopw + bias1) * rsqrt(max(deg_out,1))
    gemm_k64<false, true, true, true><<<dim3(1, MY), 256>>>(
        X, loopw, hs_d, N, 64, agg1_d, bias1, nullptr, degout_d);

    // agg2[dst] += hs[src]
    scatter2_kernel<<<(E * 16 + 255) / 256, 256>>>(E);

    // out = (agg2 * rsqrt(max(deg_in,1))) @ w2 + bias2
    gemm_k64<true, false, true, false><<<dim3(1, MY), 256>>>(
        agg2_d, w2, out, N, 64, nullptr, bias2, degin_d, nullptr);
}

// round 17
// speedup vs baseline: 1.8351x; 1.2681x over previous
#include <cuda_runtime.h>
#include <cstdint>

#define NMAX 50000
#define EMAX 1000000
#define DIN 64
#define H1 64
#define H2 64
#define RNUM 8
#define BNUM 30
#define SCAN_B 256

// ---------------- device scratch ----------------
__device__ float4 g_xr[(size_t)NMAX * 512 / 4];
__device__ float4 g_agg1[(size_t)NMAX * 64 / 4];
__device__ float4 g_agg2[(size_t)NMAX * 64 / 4];
__device__ float4 g_hs[(size_t)NMAX * 64 / 4];
__device__ int    g_deg_out[NMAX];
__device__ int    g_deg_in[NMAX];
__device__ float  g_wrelH[64 * 512];
__device__ float  g_wrelL[64 * 512];
__device__ int    g_src[EMAX];
__device__ int    g_dst[EMAX];
__device__ int    g_et [EMAX];
__device__ int    g_rowstart[NMAX + 1];
__device__ int    g_blocksum[1024];
__device__ int    g_fill[NMAX];
__device__ int2   g_epack[EMAX];      // dst-sorted: (src | et<<20, dst)
__device__ int    g_ei_is64;
__device__ int    g_et_sel;
__device__ int    g_et_is64;

__device__ __forceinline__ void red_add_v4(float* addr, float4 v) {
    asm volatile("red.global.add.v4.f32 [%0], {%1, %2, %3, %4};"
                 :: "l"(addr), "f"(v.x), "f"(v.y), "f"(v.z), "f"(v.w)
                 : "memory");
}

__device__ __forceinline__ void split_tf32(float v, uint32_t& h, uint32_t& l) {
    uint32_t hb;
    asm("cvt.rna.tf32.f32 %0, %1;" : "=r"(hb) : "f"(v));
    float r = v - __uint_as_float(hb);
    uint32_t lb;
    asm("cvt.rna.tf32.f32 %0, %1;" : "=r"(lb) : "f"(r));
    h = hb; l = lb;
}

#define MMA_TF32(d, a, b)                                                     \
    asm volatile(                                                             \
        "mma.sync.aligned.m16n8k8.row.col.f32.tf32.tf32.f32 "                \
        "{%0,%1,%2,%3}, {%4,%5,%6,%7}, {%8,%9}, {%0,%1,%2,%3};"              \
        : "+f"((d)[0]), "+f"((d)[1]), "+f"((d)[2]), "+f"((d)[3])              \
        : "r"((a)[0]), "r"((a)[1]), "r"((a)[2]), "r"((a)[3]),                 \
          "r"((b)[0]), "r"((b)[1]))

// ---------------- dtype + identity detection (1 warp per probe) ----------------
__global__ void detect_kernel(const void* ei, const void* etA, const void* etB,
                              int E, int N) {
    __shared__ int ok[5];
    int w = threadIdx.x >> 5;
    int lane = threadIdx.x & 31;
    if (w < 5) {
        const void* p = (w == 0) ? ei : (w <= 2 ? etA : etB);
        int is64 = (w == 0) || (w == 2) || (w == 4);
        int cnt  = (w == 0) ? E : ((w == 2 || w == 4) ? E / 2 : E);
        long long hi = (w == 0) ? (long long)N : 64;
        int myok = 1;
        for (int i = lane; i < 64; i += 32) {
            int stride = cnt > 64 ? cnt / 64 : 1;
            int idx = i * stride;
            if (idx < cnt) {
                long long v = is64 ? ((const long long*)p)[idx]
                                   : (long long)((const int*)p)[idx];
                if (v < 0 || v >= hi) myok = 0;
            }
        }
        unsigned m = __ballot_sync(0xFFFFFFFFu, myok);
        if (lane == 0) ok[w] = (m == 0xFFFFFFFFu);
    }
    __syncthreads();
    if (threadIdx.x == 0) {
        int A32 = ok[1], A64 = ok[2], B32 = ok[3], B64 = ok[4];
        g_ei_is64 = ok[0];
        int selA = (A32 || A64);
        int selB = (B32 || B64);
        if (selA && !selB)      { g_et_sel = 0; g_et_is64 = A64; }
        else if (selB && !selA) { g_et_sel = 1; g_et_is64 = B64; }
        else                    { g_et_sel = 1; g_et_is64 = B64; }
    }
}

// ---------------- zero scratch ----------------
__global__ void zero_kernel(int n) {
    int i = blockIdx.x * blockDim.x + threadIdx.x;
    float4 z = make_float4(0.f, 0.f, 0.f, 0.f);
    int nf4 = n * 16;
    if (i < nf4) { g_agg1[i] = z; g_agg2[i] = z; }
    if (i < n)   { g_deg_out[i] = 0; g_deg_in[i] = 0; g_fill[i] = 0; }
}

// ---------------- convert indices + degree counts ----------------
__global__ void convert_kernel(const void* ei, const void* etA, const void* etB,
                               int E, int N) {
    int e = blockIdx.x * blockDim.x + threadIdx.x;
    if (e >= E) return;
    const void* et = g_et_sel ? etB : etA;
    long long s, d, r;
    if (g_ei_is64) {
        s = ((const long long*)ei)[e];
        d = ((const long long*)ei)[E + e];
    } else {
        s = ((const int*)ei)[e];
        d = ((const int*)ei)[E + e];
    }
    if (g_et_is64) r = ((const long long*)et)[e];
    else           r = ((const int*)et)[e];
    int si = (int)s, di = (int)d, ri = (int)r;
    if (si < 0) si = 0; if (si >= N) si = N - 1;
    if (di < 0) di = 0; if (di >= N) di = N - 1;
    ri &= 7;
    g_src[e] = si; g_dst[e] = di; g_et[e] = ri;
    atomicAdd(&g_deg_out[si], 1);
    atomicAdd(&g_deg_in[di], 1);
}

// ---------------- exclusive scan of deg_in -> rowstart ----------------
__global__ void scanA_kernel(int n) {
    __shared__ int sh[SCAN_B];
    int i = blockIdx.x * SCAN_B + threadIdx.x;
    int v = (i < n) ? g_deg_in[i] : 0;
    sh[threadIdx.x] = v;
    __syncthreads();
#pragma unroll
    for (int off = 1; off < SCAN_B; off <<= 1) {
        int t = (threadIdx.x >= off) ? sh[threadIdx.x - off] : 0;
        __syncthreads();
        sh[threadIdx.x] += t;
        __syncthreads();
    }
    if (i < n) g_rowstart[i] = sh[threadIdx.x] - v;
    if (threadIdx.x == SCAN_B - 1) g_blocksum[blockIdx.x] = sh[threadIdx.x];
}
__global__ void scanB_kernel(int nb) {
    __shared__ int sh[1024];
    int v = (threadIdx.x < nb) ? g_blocksum[threadIdx.x] : 0;
    sh[threadIdx.x] = v;
    __syncthreads();
#pragma unroll
    for (int off = 1; off < 1024; off <<= 1) {
        int t = (threadIdx.x >= off) ? sh[threadIdx.x - off] : 0;
        __syncthreads();
        sh[threadIdx.x] += t;
        __syncthreads();
    }
    if (threadIdx.x < nb) g_blocksum[threadIdx.x] = sh[threadIdx.x] - v;
}
__global__ void scanC_kernel(int n, int E) {
    int i = blockIdx.x * SCAN_B + threadIdx.x;
    if (i < n) g_rowstart[i] += g_blocksum[blockIdx.x];
    if (i == 0) g_rowstart[n] = E;
}

// ---------------- fill: dst-sorted packed edges ----------------
__global__ void fill_kernel(int E) {
    int e = blockIdx.x * blockDim.x + threadIdx.x;
    if (e >= E) return;
    int d = g_dst[e];
    int slot = g_rowstart[d] + atomicAdd(&g_fill[d], 1);
    g_epack[slot] = make_int2(g_src[e] | (g_et[e] << 20), d);
}

// ---------------- Wrel^T -> tf32 hi/lo ----------------
__global__ void wrel_kernel(const float* __restrict__ comp,
                            const float* __restrict__ basis) {
    int idx = blockIdx.x * blockDim.x + threadIdx.x;
    if (idx >= 64 * 512) return;
    int k = idx >> 9;
    int rem = idx & 511;
    int r = rem >> 6;
    int o = rem & 63;
    float s = 0.f;
#pragma unroll
    for (int b = 0; b < BNUM; b++)
        s = fmaf(comp[r * BNUM + b], basis[b * (DIN * H1) + k * H1 + o], s);
    uint32_t h, l;
    split_tf32(s, h, l);
    g_wrelH[idx] = __uint_as_float(h);
    g_wrelL[idx] = __uint_as_float(l);
}

// ---------------- tensor-core GEMM (xr) ----------------
#define AS_STRIDE 68
#define BS_STRIDE 136
__global__ __launch_bounds__(256) void gemm_xr_tc(
    const float* __restrict__ A, const float* __restrict__ Bh,
    const float* __restrict__ Bl, float* __restrict__ C, int M)
{
    extern __shared__ float sm[];
    float* As  = sm;
    float* Bhs = sm + 128 * AS_STRIDE;
    float* Bls = Bhs + 64 * BS_STRIDE;

    const int tid  = threadIdx.x;
    const int warp = tid >> 5;
    const int lane = tid & 31;
    const int g    = lane >> 2;
    const int tig  = lane & 3;
    const int row0 = blockIdx.y * 128;
    const int col0 = blockIdx.x * 128;

#pragma unroll
    for (int i = 0; i < 8; i++) {
        int j = tid + i * 256;
        int r = j >> 4;
        int c4 = j & 15;
        int row = row0 + r;
        float4 v = make_float4(0.f, 0.f, 0.f, 0.f);
        if (row < M) v = *(const float4*)(A + (size_t)row * 64 + c4 * 4);
        *(float4*)&As[r * AS_STRIDE + c4 * 4] = v;
    }
#pragma unroll
    for (int i = 0; i < 8; i++) {
        int j = tid + i * 256;
        int k = j >> 5;
        int c4 = j & 31;
        *(float4*)&Bhs[k * BS_STRIDE + c4 * 4] =
            *(const float4*)(Bh + (size_t)k * 512 + col0 + c4 * 4);
        *(float4*)&Bls[k * BS_STRIDE + c4 * 4] =
            *(const float4*)(Bl + (size_t)k * 512 + col0 + c4 * 4);
    }
    __syncthreads();

    const int m0 = (warp & 3) * 32;
    const int n0 = (warp >> 2) * 64;

    float d[2][8][4];
#pragma unroll
    for (int mf = 0; mf < 2; mf++)
#pragma unroll
        for (int nf = 0; nf < 8; nf++)
#pragma unroll
            for (int q = 0; q < 4; q++) d[mf][nf][q] = 0.f;

#pragma unroll
    for (int ks = 0; ks < 64; ks += 8) {
        uint32_t ah[2][4], al[2][4];
#pragma unroll
        for (int mf = 0; mf < 2; mf++) {
            int rm = m0 + mf * 16 + g;
            float v0 = As[(rm)     * AS_STRIDE + ks + tig];
            float v1 = As[(rm + 8) * AS_STRIDE + ks + tig];
            float v2 = As[(rm)     * AS_STRIDE + ks + tig + 4];
            float v3 = As[(rm + 8) * AS_STRIDE + ks + tig + 4];
            split_tf32(v0, ah[mf][0], al[mf][0]);
            split_tf32(v1, ah[mf][1], al[mf][1]);
            split_tf32(v2, ah[mf][2], al[mf][2]);
            split_tf32(v3, ah[mf][3], al[mf][3]);
        }
        uint32_t bhf[8][2], blf[8][2];
#pragma unroll
        for (int nf = 0; nf < 8; nf++) {
            int c = n0 + nf * 8 + g;
            bhf[nf][0] = __float_as_uint(Bhs[(ks + tig)     * BS_STRIDE + c]);
            bhf[nf][1] = __float_as_uint(Bhs[(ks + tig + 4) * BS_STRIDE + c]);
            blf[nf][0] = __float_as_uint(Bls[(ks + tig)     * BS_STRIDE + c]);
            blf[nf][1] = __float_as_uint(Bls[(ks + tig + 4) * BS_STRIDE + c]);
        }
#pragma unroll
        for (int mf = 0; mf < 2; mf++)
#pragma unroll
            for (int nf = 0; nf < 8; nf++) {
                MMA_TF32(d[mf][nf], ah[mf], bhf[nf]);
                MMA_TF32(d[mf][nf], al[mf], bhf[nf]);
                MMA_TF32(d[mf][nf], ah[mf], blf[nf]);
            }
    }

#pragma unroll
    for (int mf = 0; mf < 2; mf++) {
        int r0 = row0 + m0 + mf * 16 + g;
        int r1 = r0 + 8;
#pragma unroll
        for (int nf = 0; nf < 8; nf++) {
            int c = col0 + n0 + nf * 8 + 2 * tig;
            if (r0 < M)
                *(float2*)(C + (size_t)r0 * 512 + c) =
                    make_float2(d[mf][nf][0], d[mf][nf][1]);
            if (r1 < M)
                *(float2*)(C + (size_t)r1 * 512 + c) =
                    make_float2(d[mf][nf][2], d[mf][nf][3]);
        }
    }
}
#define GEMM_XR_SMEM ((128 * AS_STRIDE + 2 * 64 * BS_STRIDE) * 4)

// ---------------- small GEMM, K=64 ----------------
template<bool PRE, bool ADD, bool BIAS_, bool POST>
__global__ __launch_bounds__(256) void gemm_k64(
    const float* __restrict__ A, const float* __restrict__ B,
    float* __restrict__ C, int M, int N,
    const float* __restrict__ addend, const float* __restrict__ bias,
    const int* __restrict__ predeg, const int* __restrict__ postdeg)
{
    __shared__ float As[32][132];
    __shared__ float Bs[32][64];

    const int tid = threadIdx.x;
    const int row0 = blockIdx.y * 128;
    const int col0 = blockIdx.x * 64;

    float acc[8][4];
#pragma unroll
    for (int r = 0; r < 8; r++)
#pragma unroll
        for (int c = 0; c < 4; c++) acc[r][c] = 0.f;

    const int tm = tid >> 4;
    const int tn = tid & 15;

    for (int ks = 0; ks < 64; ks += 32) {
#pragma unroll
        for (int i = 0; i < 4; i++) {
            int j = tid + i * 256;
            int r = j >> 3;
            int c4 = j & 7;
            int row = row0 + r;
            float4 v = make_float4(0.f, 0.f, 0.f, 0.f);
            if (row < M) {
                v = *(const float4*)(A + (size_t)row * 64 + ks + c4 * 4);
                if (PRE) {
                    float s = rsqrtf(fmaxf((float)predeg[row], 1.0f));
                    v.x *= s; v.y *= s; v.z *= s; v.w *= s;
                }
            }
            As[c4 * 4 + 0][r] = v.x;
            As[c4 * 4 + 1][r] = v.y;
            As[c4 * 4 + 2][r] = v.z;
            As[c4 * 4 + 3][r] = v.w;
        }
#pragma unroll
        for (int i = 0; i < 2; i++) {
            int j = tid + i * 256;
            int r = j >> 4;
            int c4 = j & 15;
            *(float4*)&Bs[r][c4 * 4] =
                *(const float4*)(B + (size_t)(ks + r) * N + col0 + c4 * 4);
        }
        __syncthreads();

#pragma unroll
        for (int k = 0; k < 32; k++) {
            float a[8], b[4];
            *(float4*)&a[0] = *(const float4*)&As[k][tm * 8];
            *(float4*)&a[4] = *(const float4*)&As[k][tm * 8 + 4];
            *(float4*)&b[0] = *(const float4*)&Bs[k][tn * 4];
#pragma unroll
            for (int r = 0; r < 8; r++)
#pragma unroll
                for (int c = 0; c < 4; c++)
                    acc[r][c] = fmaf(a[r], b[c], acc[r][c]);
        }
        __syncthreads();
    }

#pragma unroll
    for (int r = 0; r < 8; r++) {
        int row = row0 + tm * 8 + r;
        if (row >= M) break;
        float ps = 1.f;
        if (POST) ps = rsqrtf(fmaxf((float)postdeg[row], 1.0f));
#pragma unroll
        for (int c = 0; c < 4; c++) {
            int col = col0 + tn * 4 + c;
            float v = acc[r][c];
            if (ADD)   v += addend[(size_t)row * N + col];
            if (BIAS_) v += bias[col];
            if (POST)  v *= ps;
            C[(size_t)row * N + col] = v;
        }
    }
}

// ---------------- sorted scatter 1: agg1 += xr[src,et] with run combining ----------------
// Thread = (chunk of 8 sorted edges, q). Batch loads (MLP=8), combine runs,
// red only at run boundaries (~1.35 reds/thread at avg degree 20).
__global__ __launch_bounds__(256) void scatter1s_kernel(int E) {
    int t = blockIdx.x * blockDim.x + threadIdx.x;
    int nch = (E + 7) >> 3;
    if (t >= nch * 16) return;
    int c = t >> 4;
    int q = t & 15;
    int base = c * 8;

    int dj[8], sj[8], rj[8];
#pragma unroll
    for (int j = 0; j < 8; j++) {
        int idx = base + j;
        int2 p = g_epack[idx < E ? idx : E - 1];
        dj[j] = (idx < E) ? p.y : -1;
        sj[j] = p.x & 0xFFFFF;
        rj[j] = p.x >> 20;
    }
    float4 v[8];
#pragma unroll
    for (int j = 0; j < 8; j++)
        v[j] = g_xr[(size_t)sj[j] * 128 + rj[j] * 16 + q];

    float4 acc = v[0];
    int curd = dj[0];
#pragma unroll
    for (int j = 1; j < 8; j++) {
        if (dj[j] == curd) {
            acc.x += v[j].x; acc.y += v[j].y; acc.z += v[j].z; acc.w += v[j].w;
        } else {
            if (curd >= 0)
                red_add_v4((float*)g_agg1 + (size_t)curd * 64 + q * 4, acc);
            acc = v[j];
            curd = dj[j];
        }
    }
    if (curd >= 0)
        red_add_v4((float*)g_agg1 + (size_t)curd * 64 + q * 4, acc);
}

// ---------------- sorted scatter 2: agg2 += hs[src] ----------------
__global__ __launch_bounds__(256) void scatter2s_kernel(int E) {
    int t = blockIdx.x * blockDim.x + threadIdx.x;
    int nch = (E + 7) >> 3;
    if (t >= nch * 16) return;
    int c = t >> 4;
    int q = t & 15;
    int base = c * 8;

    int dj[8], sj[8];
#pragma unroll
    for (int j = 0; j < 8; j++) {
        int idx = base + j;
        int2 p = g_epack[idx < E ? idx : E - 1];
        dj[j] = (idx < E) ? p.y : -1;
        sj[j] = p.x & 0xFFFFF;
    }
    float4 v[8];
#pragma unroll
    for (int j = 0; j < 8; j++)
        v[j] = g_hs[(size_t)sj[j] * 16 + q];

    float4 acc = v[0];
    int curd = dj[0];
#pragma unroll
    for (int j = 1; j < 8; j++) {
        if (dj[j] == curd) {
            acc.x += v[j].x; acc.y += v[j].y; acc.z += v[j].z; acc.w += v[j].w;
        } else {
            if (curd >= 0)
                red_add_v4((float*)g_agg2 + (size_t)curd * 64 + q * 4, acc);
            acc = v[j];
            curd = dj[j];
        }
    }
    if (curd >= 0)
        red_add_v4((float*)g_agg2 + (size_t)curd * 64 + q * 4, acc);
}

// ---------------- launch ----------------
extern "C" void kernel_launch(void* const* d_in, const int* in_sizes, int n_in,
                              void* d_out, int out_size) {
    const float *X = nullptr, *basis = nullptr, *comp = nullptr;
    const float *loopw = nullptr, *bias1 = nullptr, *w2 = nullptr, *bias2 = nullptr;
    const void  *ei = nullptr, *etA = nullptr, *etB = nullptr;
    int E = EMAX;
    {
        int seen4096 = 0, seen64 = 0;
        long long maxsz = 0;
        for (int i = 0; i < n_in; i++) if (in_sizes[i] > maxsz) maxsz = in_sizes[i];
        for (int i = 0; i < n_in; i++)
            if (in_sizes[i] == maxsz && X == nullptr) X = (const float*)d_in[i];
        long long second = 0;
        for (int i = 0; i < n_in; i++) {
            long long sz = in_sizes[i];
            if (sz < maxsz && sz > second) second = sz;
        }
        E = (int)(second / 2);
        for (int i = 0; i < n_in; i++) {
            long long sz = in_sizes[i];
            const void* p = d_in[i];
            if (sz == maxsz && p == (const void*)X) continue;
            if (sz == second && ei == nullptr) { ei = p; continue; }
            if (sz == (long long)E) {
                if (etA == nullptr) etA = p; else etB = p;
                continue;
            }
            if (sz == 122880) { basis = (const float*)p; continue; }
            if (sz == 240)    { comp  = (const float*)p; continue; }
            if (sz == 4096) {
                if (seen4096 == 0) { loopw = (const float*)p; seen4096 = 1; }
                else               { w2    = (const float*)p; }
                continue;
            }
            if (sz == 64) {
                if (seen64 == 0) { bias1 = (const float*)p; seen64 = 1; }
                else             { bias2 = (const float*)p; }
                continue;
            }
        }
    }
    float* out = (float*)d_out;
    const int N = out_size / H2;

    void *p_xr_, *p_agg1_, *p_agg2_, *p_hs_, *p_do_, *p_di_, *p_wh_, *p_wl_;
    cudaGetSymbolAddress(&p_xr_,   g_xr);
    cudaGetSymbolAddress(&p_agg1_, g_agg1);
    cudaGetSymbolAddress(&p_agg2_, g_agg2);
    cudaGetSymbolAddress(&p_hs_,   g_hs);
    cudaGetSymbolAddress(&p_do_,   g_deg_out);
    cudaGetSymbolAddress(&p_di_,   g_deg_in);
    cudaGetSymbolAddress(&p_wh_,   g_wrelH);
    cudaGetSymbolAddress(&p_wl_,   g_wrelL);
    float* xr_d     = (float*)p_xr_;
    float* agg1_d   = (float*)p_agg1_;
    float* agg2_d   = (float*)p_agg2_;
    float* hs_d     = (float*)p_hs_;
    int*   degout_d = (int*)p_do_;
    int*   degin_d  = (int*)p_di_;
    float* wrelH_d  = (float*)p_wh_;
    float* wrelL_d  = (float*)p_wl_;

    detect_kernel<<<1, 160>>>(ei, etA, etB, E, N);

    const int ZB = (N * 16 + 255) / 256;
    zero_kernel<<<ZB, 256>>>(N);

    convert_kernel<<<(E + 255) / 256, 256>>>(ei, etA, etB, E, N);

    // dst-sorted edge build
    const int NSB = (N + SCAN_B - 1) / SCAN_B;
    scanA_kernel<<<NSB, SCAN_B>>>(N);
    scanB_kernel<<<1, 1024>>>(NSB);
    scanC_kernel<<<NSB, SCAN_B>>>(N, E);
    fill_kernel<<<(E + 255) / 256, 256>>>(E);

    wrel_kernel<<<(64 * 512 + 255) / 256, 256>>>(comp, basis);

    const int MY = (N + 127) / 128;

    cudaFuncSetAttribute(gemm_xr_tc, cudaFuncAttributeMaxDynamicSharedMemorySize,
                         GEMM_XR_SMEM);
    gemm_xr_tc<<<dim3(4, MY), 256, GEMM_XR_SMEM>>>(X, wrelH_d, wrelL_d, xr_d, N);

    const int NCH = (E + 7) / 8;
    scatter1s_kernel<<<(NCH * 16 + 255) / 256, 256>>>(E);

    gemm_k64<false, true, true, true><<<dim3(1, MY), 256>>>(
        X, loopw, hs_d, N, 64, agg1_d, bias1, nullptr, degout_d);

    scatter2s_kernel<<<(NCH * 16 + 255) / 256, 256>>>(E);

    gemm_k64<true, false, true, false><<<dim3(1, MY), 256>>>(
        agg2_d, w2, out, N, 64, nullptr, bias2, degin_d, nullptr);
}